// round 16
// baseline (speedup 1.0000x reference)
#include <cuda_runtime.h>
#include <cuda_bf16.h>
#include <cuda_fp16.h>
#include <cstdint>

// ---------------------------------------------------------------------------
// Problem constants
// ---------------------------------------------------------------------------
constexpr int B_  = 2;
constexpr int S_  = 1024;
constexpr int H_  = 4096;
constexpr int N_  = 64;
constexpr int NOPE_ = 128;
constexpr int ROPE_ = 64;
constexpr int V_  = 128;
constexpr int KV_LORA_ = 512;
constexpr int Q_LORA_  = 1536;
constexpr int QK_ = NOPE_ + ROPE_;           // 192
constexpr int CAT_ = KV_LORA_ + ROPE_;       // 576
constexpr int PROJ_ = Q_LORA_ + CAT_;        // 2112
constexpr int MS_ = B_ * S_;                 // 2048
constexpr float SCALE_ = 0.072168783648703220563f; // 192^-0.5
constexpr float EPS_ = 1e-6f;

// ---------------------------------------------------------------------------
// Scratch (device globals; allocation is forbidden)
// ---------------------------------------------------------------------------
__device__ float g_qkva  [(size_t)MS_ * PROJ_];
__device__ float g_scores[(size_t)B_ * N_ * S_ * S_];

__device__ __half g_hs_f  [(size_t)MS_ * H_];
__device__ __half g_qan_f [(size_t)MS_ * Q_LORA_];
__device__ __half g_q_f   [(size_t)MS_ * N_ * QK_];
__device__ __half g_qcat_f[(size_t)MS_ * N_ * CAT_];
__device__ __half g_attn_f[(size_t)B_ * N_ * S_ * S_];
__device__ __half g_ol_f  [(size_t)MS_ * N_ * KV_LORA_];
__device__ __half g_op_f  [(size_t)MS_ * N_ * V_];

__device__ __half g_pw_f [(size_t)PROJ_ * H_];
__device__ __half g_qbw_f[(size_t)N_ * QK_ * Q_LORA_];
__device__ __half g_ukT_f[(size_t)N_ * KV_LORA_ * NOPE_];
__device__ __half g_kvbw_f[(size_t)N_ * (NOPE_+V_) * KV_LORA_];
__device__ __half g_kcat_f[(size_t)MS_ * CAT_];
__device__ __half g_kT_f [(size_t)B_ * KV_LORA_ * S_];
__device__ __half g_ow_f [(size_t)H_ * N_ * V_];

// ---------------------------------------------------------------------------
// PTX helpers
// ---------------------------------------------------------------------------
__device__ __forceinline__ void ldsm4(uint32_t* r, const void* p) {
    uint32_t addr = (uint32_t)__cvta_generic_to_shared(p);
    asm volatile("ldmatrix.sync.aligned.m8n8.x4.shared.b16 {%0,%1,%2,%3}, [%4];"
                 : "=r"(r[0]), "=r"(r[1]), "=r"(r[2]), "=r"(r[3]) : "r"(addr));
}
__device__ __forceinline__ void mma_f16(float* d, const uint32_t* a,
                                        uint32_t b0, uint32_t b1) {
    asm volatile("mma.sync.aligned.m16n8k16.row.col.f32.f16.f16.f32 "
                 "{%0,%1,%2,%3}, {%4,%5,%6,%7}, {%8,%9}, {%0,%1,%2,%3};"
                 : "+f"(d[0]), "+f"(d[1]), "+f"(d[2]), "+f"(d[3])
                 : "r"(a[0]), "r"(a[1]), "r"(a[2]), "r"(a[3]), "r"(b0), "r"(b1));
}
__device__ __forceinline__ void cp16(void* dst, const void* src) {
    uint32_t d = (uint32_t)__cvta_generic_to_shared(dst);
    asm volatile("cp.async.cg.shared.global [%0], [%1], 16;\n" :: "r"(d), "l"(src));
}
__device__ __forceinline__ void cp_commit() { asm volatile("cp.async.commit_group;\n"); }
template <int W> __device__ __forceinline__ void cp_wait() {
    asm volatile("cp.async.wait_group %0;\n" :: "n"(W));
}

// ---------------------------------------------------------------------------
// fp16 1-term GEMM: C = A @ B^T, single fp16 planes.
// NT=64 : 256 thr, 8 warps (4m x 2n), 2 CTAs/SM.
// NT=128: 512 thr, 16 warps (4m x 4n), 1 CTA/SM — 64 FLOP/B from L2
//         (vs 43 at NT=64): relieves the L2-bandwidth bound.
// Warp tile 32x32 (MSUB=2) both. 3-stage cp.async, single sync per iter,
// 8-deep accumulator ILP. OMODE: 0=fp32 out, 2=fp16 out.
// CSKIP: skip tiles above causal diagonal. CKLIM: clip K at m0+128.
// ---------------------------------------------------------------------------
constexpr int SKA = 40;

#define A_EL_           (128 * SKA)
#define STAGE_EL_(NT)   ((128 + (NT)) * SKA)
#define SMEM_BYTES_(NT) (3 * STAGE_EL_(NT) * 2)

extern __shared__ uint16_t smem_dyn[];

template <int NT, int TPB, int OMODE, bool CSKIP, bool CKLIM>
__global__ __launch_bounds__(TPB, (NT == 64) ? 2 : 1)
void gemm_f(const __half* __restrict__ A_,
            const __half* __restrict__ B_p,
            float* __restrict__ Cf, __half* __restrict__ Ch_,
            int K, int lda, int ldb, int ldc,
            long long sA1, long long sA2,
            long long sB1, long long sB2,
            long long sC1, long long sC2, int D2)
{
    constexpr int MSUB = 2;
    constexpr int B_EL = NT * SKA;
    constexpr int STG  = STAGE_EL_(NT);

    const int m0 = blockIdx.y * 128;
    const int n0 = blockIdx.x * NT;
    if (CSKIP && n0 > m0 + 127) return;

    const int tid  = threadIdx.x;
    const int lane = tid & 31;
    const int w    = tid >> 5;
    const int wm   = w & 3;
    const int wn   = w >> 2;

    const int bz = blockIdx.z;
    const int i1 = bz / D2;
    const int i2 = bz - i1 * D2;
    const long long offA = (long long)i1 * sA1 + (long long)i2 * sA2;
    const long long offB = (long long)i1 * sB1 + (long long)i2 * sB2;
    const long long offC = (long long)i1 * sC1 + (long long)i2 * sC2;
    const uint16_t* Ab = (const uint16_t*)A_  + offA;
    const uint16_t* Bb = (const uint16_t*)B_p + offB;

    int Keff = K;
    if (CKLIM) Keff = (K < m0 + 128) ? K : (m0 + 128);
    const int nk = Keff >> 5;

    float acc[MSUB][4][4];
    #pragma unroll
    for (int i = 0; i < MSUB; i++)
        #pragma unroll
        for (int j = 0; j < 4; j++)
            #pragma unroll
            for (int t = 0; t < 4; t++) acc[i][j][t] = 0.f;

    auto load_stage = [&](int stg, int k0) {
        uint16_t* base = smem_dyn + stg * STG;
        #pragma unroll
        for (int j = 0; j < 512 / TPB; j++) {    // A: 512 16B chunks
            int idx = tid + j * TPB;
            int r = idx >> 2;
            int c = idx & 3;
            const uint16_t* src = Ab + (size_t)(m0 + r) * lda + k0 + c * 8;
            cp16(base + r * SKA + c * 8, src);
        }
        // B: NT*4 16B chunks (NT=64: 256 of 256 thr; NT=128: 512 of 512 thr)
        if (NT * 4 >= TPB) {
            #pragma unroll
            for (int j = 0; j < (NT * 4) / TPB; j++) {
                int idx = tid + j * TPB;
                int r = idx >> 2;
                int c = idx & 3;
                const uint16_t* src = Bb + (size_t)(n0 + r) * ldb + k0 + c * 8;
                cp16(base + A_EL_ + r * SKA + c * 8, src);
            }
        } else if (tid < NT * 4) {
            int r = tid >> 2;
            int c = tid & 3;
            const uint16_t* src = Bb + (size_t)(n0 + r) * ldb + k0 + c * 8;
            cp16(base + A_EL_ + r * SKA + c * 8, src);
        }
    };

    load_stage(0, 0);
    cp_commit();
    if (nk > 1) load_stage(1, 32);
    cp_commit();

    int stg = 0;
    for (int i = 0; i < nk; i++) {
        cp_wait<1>();
        __syncthreads();
        int nxt = stg + 2; if (nxt >= 3) nxt -= 3;
        if (i + 2 < nk) load_stage(nxt, (i + 2) << 5);
        cp_commit();

        const uint16_t* sA = smem_dyn + stg * STG;
        const uint16_t* sB = sA + A_EL_;

        #pragma unroll
        for (int kk = 0; kk < 32; kk += 16) {
            uint32_t af[MSUB][4];
            const int ar = wm * 32 + (lane & 15);
            const int ac = kk + ((lane >> 4) << 3);
            #pragma unroll
            for (int mi = 0; mi < MSUB; mi++)
                ldsm4(af[mi], sA + (ar + mi * 16) * SKA + ac);

            uint32_t bf[2][4];
            const int br = wn * 32 + (lane & 7) + ((lane >> 4) << 3);
            const int bc = kk + (((lane >> 3) & 1) << 3);
            ldsm4(bf[0], sB + br * SKA + bc);
            ldsm4(bf[1], sB + (br + 16) * SKA + bc);

            // 8 independent accumulators between RAW reuses
            #pragma unroll
            for (int mi = 0; mi < MSUB; mi++) {
                #pragma unroll
                for (int ni = 0; ni < 4; ni++) {
                    const int p = ni >> 1, q = (ni & 1) * 2;
                    mma_f16(acc[mi][ni], af[mi], bf[p][q], bf[p][q + 1]);
                }
            }
        }
        stg = stg + 1; if (stg == 3) stg = 0;
    }

    // epilogue
    const int lr = lane >> 2;
    const int lc = (lane & 3) * 2;
    #pragma unroll
    for (int mi = 0; mi < MSUB; mi++) {
        #pragma unroll
        for (int ni = 0; ni < 4; ni++) {
            size_t row = (size_t)(m0 + wm * 32 + mi * 16 + lr);
            int    col = n0 + wn * 32 + ni * 8 + lc;
            size_t o0 = offC + row * ldc + col;
            size_t o1 = offC + (row + 8) * ldc + col;
            if (OMODE == 0) {
                *(float2*)&Cf[o0] = make_float2(acc[mi][ni][0], acc[mi][ni][1]);
                *(float2*)&Cf[o1] = make_float2(acc[mi][ni][2], acc[mi][ni][3]);
            } else {
                *(__half2*)&Ch_[o0] = {__float2half(acc[mi][ni][0]), __float2half(acc[mi][ni][1])};
                *(__half2*)&Ch_[o1] = {__float2half(acc[mi][ni][2]), __float2half(acc[mi][ni][3])};
            }
        }
    }
}

// ---------------------------------------------------------------------------
// Segmented conversion: fp32 -> fp16 single plane
// ---------------------------------------------------------------------------
struct ConvSeg { const float* s; __half* h; size_t off; };
struct ConvTable { ConvSeg seg[6]; size_t total; };

__global__ void conv_all(ConvTable t)
{
    size_t i = (size_t)blockIdx.x * blockDim.x + threadIdx.x;
    if (i >= t.total) return;
    int k = 0;
    #pragma unroll
    for (int j = 1; j < 6; j++) if (i >= t.seg[j].off) k = j;
    size_t li = i - t.seg[k].off;
    float4 v = ((const float4*)t.seg[k].s)[li];
    ((__half2*)t.seg[k].h)[2*li]   = {__float2half(v.x), __float2half(v.y)};
    ((__half2*)t.seg[k].h)[2*li+1] = {__float2half(v.z), __float2half(v.w)};
}

__global__ void conv_ukT(const float* __restrict__ w, __half* __restrict__ h)
{
    size_t i = (size_t)blockIdx.x * blockDim.x + threadIdx.x;
    if (i >= (size_t)N_ * KV_LORA_ * NOPE_) return;
    int d = (int)(i & (NOPE_ - 1));
    int c = (int)((i >> 7) & (KV_LORA_ - 1));
    int n = (int)(i >> 16);
    h[i] = __float2half(w[(size_t)n * ((NOPE_+V_) * KV_LORA_) + (size_t)d * KV_LORA_ + c]);
}

__global__ void rmsnorm_f16(const float* __restrict__ x, const float* __restrict__ w,
                            __half* __restrict__ of, int cols, int ld)
{
    __shared__ float red[256];
    const float* row = x + (size_t)blockIdx.x * ld;
    __half* rf = of + (size_t)blockIdx.x * cols;
    int tid = threadIdx.x;
    float ss = 0.f;
    for (int c = tid; c < cols; c += 256) { float v = row[c]; ss += v * v; }
    red[tid] = ss; __syncthreads();
    for (int o = 128; o > 0; o >>= 1) { if (tid < o) red[tid] += red[tid + o]; __syncthreads(); }
    float r = rsqrtf(red[0] / cols + EPS_);
    for (int c = tid; c < cols; c += 256) rf[c] = __float2half(row[c] * r * w[c]);
}

__global__ void kv_process_f16(const float* __restrict__ kva, const float* __restrict__ lnw,
                               const float* __restrict__ cosb, const float* __restrict__ sinb,
                               const int* __restrict__ pid, int ld,
                               __half* __restrict__ kcf, __half* __restrict__ kTf)
{
    __shared__ float red[256];
    int row = blockIdx.x;
    int b = row >> 10, t = row & (S_ - 1);
    const float* x = kva + (size_t)row * ld;
    __half* y = kcf + (size_t)row * CAT_;
    int tid = threadIdx.x;
    float ss = 0.f;
    for (int c = tid; c < KV_LORA_; c += 256) { float v = x[c]; ss += v * v; }
    red[tid] = ss; __syncthreads();
    for (int o = 128; o > 0; o >>= 1) { if (tid < o) red[tid] += red[tid + o]; __syncthreads(); }
    float r = rsqrtf(red[0] / KV_LORA_ + EPS_);
    for (int c = tid; c < KV_LORA_; c += 256) {
        __half h = __float2half(x[c] * r * lnw[c]);
        y[c] = h;
        kTf[((size_t)b * KV_LORA_ + c) * S_ + t] = h;
    }
    if (tid < 32) {
        int pos = pid[row];
        const float* cp = cosb + (size_t)pos * ROPE_;
        const float* sp = sinb + (size_t)pos * ROPE_;
        int i = tid;
        float x1 = x[KV_LORA_ + i], x2 = x[KV_LORA_ + i + 32];
        y[KV_LORA_ + i]      = __float2half(x1 * cp[i] - x2 * sp[i]);
        y[KV_LORA_ + i + 32] = __float2half(x2 * cp[i + 32] + x1 * sp[i + 32]);
    }
}

__global__ void q_rope_f16(const __half* __restrict__ qf,
                           const float* __restrict__ cosb, const float* __restrict__ sinb,
                           const int* __restrict__ pid, __half* __restrict__ ocf)
{
    size_t idx = (size_t)blockIdx.x * blockDim.x + threadIdx.x;
    if (idx >= (size_t)MS_ * N_ * 32) return;
    int i = (int)(idx & 31);
    size_t r = idx >> 5;
    int n = (int)(r & (N_ - 1));
    size_t m = r >> 6;
    int pos = pid[m];
    size_t src = m * (size_t)(N_ * QK_) + (size_t)n * QK_ + NOPE_;
    size_t dst = m * (size_t)(N_ * CAT_) + (size_t)n * CAT_ + KV_LORA_;
    float x1 = __half2float(qf[src + i]);
    float x2 = __half2float(qf[src + i + 32]);
    float c1 = cosb[(size_t)pos * ROPE_ + i],      s1 = sinb[(size_t)pos * ROPE_ + i];
    float c2 = cosb[(size_t)pos * ROPE_ + i + 32], s2 = sinb[(size_t)pos * ROPE_ + i + 32];
    ocf[dst + i]      = __float2half(x1 * c1 - x2 * s1);
    ocf[dst + i + 32] = __float2half(x2 * c2 + x1 * s2);
}

__global__ void softmax_f16(float* __restrict__ scores, __half* __restrict__ af)
{
    __shared__ float red[256];
    int r = blockIdx.x;
    int s = r & (S_ - 1);
    float* x = scores + (size_t)r * S_;
    __half* of = af + (size_t)r * S_;
    int tid = threadIdx.x;

    float mx = -1e30f;
    for (int t = tid; t <= s; t += 256) mx = fmaxf(mx, x[t] * SCALE_);
    red[tid] = mx; __syncthreads();
    for (int o = 128; o > 0; o >>= 1) { if (tid < o) red[tid] = fmaxf(red[tid], red[tid + o]); __syncthreads(); }
    mx = red[0]; __syncthreads();

    float sum = 0.f;
    for (int t = tid; t <= s; t += 256) {
        float e = __expf(x[t] * SCALE_ - mx);
        x[t] = e;
        sum += e;
    }
    red[tid] = sum; __syncthreads();
    for (int o = 128; o > 0; o >>= 1) { if (tid < o) red[tid] += red[tid + o]; __syncthreads(); }
    float inv = 1.f / red[0];

    for (int t = tid; t <= s; t += 256) of[t] = __float2half(x[t] * inv);
    int zend = ((s >> 7) + 1) << 7;
    __half z = __float2half(0.f);
    for (int t = s + 1 + tid; t < zend; t += 256) of[t] = z;
}

// ---------------------------------------------------------------------------
// Host launch
// ---------------------------------------------------------------------------
struct GArgs {
    const __half *A, *Bp;
    float* Cf; __half* Ch;
    int M, N, K, lda, ldb, ldc;
    long long sA1, sA2, sB1, sB2, sC1, sC2;
    int D1, D2;
};

template <int NT, int TPB, int OMODE, bool CSKIP, bool CKLIM>
static inline void run_gemm(const GArgs& a)
{
    dim3 grid(a.N / NT, a.M / 128, a.D1 * a.D2);
    gemm_f<NT, TPB, OMODE, CSKIP, CKLIM><<<grid, TPB, SMEM_BYTES_(NT)>>>(
        a.A, a.Bp, a.Cf, a.Ch,
        a.K, a.lda, a.ldb, a.ldc, a.sA1, a.sA2, a.sB1, a.sB2, a.sC1, a.sC2, a.D2);
}

extern "C" void kernel_launch(void* const* d_in, const int* in_sizes, int n_in,
                              void* d_out, int out_size)
{
    const float* hs        = (const float*)d_in[0];
    const int*   pid       = (const int*)d_in[1];
    const float* cosb      = (const float*)d_in[2];
    const float* sinb      = (const float*)d_in[3];
    const float* q_a_w     = (const float*)d_in[4];
    const float* q_a_ln_w  = (const float*)d_in[5];
    const float* q_b_w     = (const float*)d_in[6];
    const float* kv_a_w    = (const float*)d_in[7];
    const float* kv_a_ln_w = (const float*)d_in[8];
    const float* kv_b_w    = (const float*)d_in[9];
    const float* o_w       = (const float*)d_in[10];
    float*       out       = (float*)d_out;

    static bool attr_set = false;
    if (!attr_set) {
        cudaFuncSetAttribute(gemm_f<64, 256,0,false,false>, cudaFuncAttributeMaxDynamicSharedMemorySize, SMEM_BYTES_(64));
        cudaFuncSetAttribute(gemm_f<128,512,2,false,false>, cudaFuncAttributeMaxDynamicSharedMemorySize, SMEM_BYTES_(128));
        cudaFuncSetAttribute(gemm_f<128,512,0,true, false>, cudaFuncAttributeMaxDynamicSharedMemorySize, SMEM_BYTES_(128));
        cudaFuncSetAttribute(gemm_f<128,512,2,false,true >, cudaFuncAttributeMaxDynamicSharedMemorySize, SMEM_BYTES_(128));
        cudaFuncSetAttribute(gemm_f<128,512,0,false,false>, cudaFuncAttributeMaxDynamicSharedMemorySize, SMEM_BYTES_(128));
        attr_set = true;
    }

    float *qkva, *scores;
    cudaGetSymbolAddress((void**)&qkva,   g_qkva);
    cudaGetSymbolAddress((void**)&scores, g_scores);

    __half *hs_f,*qan_f,*q_f,*qcat_f,*attn_f,*ol_f,*op_f;
    __half *pw_f,*qbw_f,*ukT_f,*kvbw_f,*kcat_f,*kT_f,*ow_f;
    cudaGetSymbolAddress((void**)&hs_f, g_hs_f);
    cudaGetSymbolAddress((void**)&qan_f, g_qan_f);
    cudaGetSymbolAddress((void**)&q_f, g_q_f);
    cudaGetSymbolAddress((void**)&qcat_f, g_qcat_f);
    cudaGetSymbolAddress((void**)&attn_f, g_attn_f);
    cudaGetSymbolAddress((void**)&ol_f, g_ol_f);
    cudaGetSymbolAddress((void**)&op_f, g_op_f);
    cudaGetSymbolAddress((void**)&pw_f, g_pw_f);
    cudaGetSymbolAddress((void**)&qbw_f, g_qbw_f);
    cudaGetSymbolAddress((void**)&ukT_f, g_ukT_f);
    cudaGetSymbolAddress((void**)&kvbw_f, g_kvbw_f);
    cudaGetSymbolAddress((void**)&kcat_f, g_kcat_f);
    cudaGetSymbolAddress((void**)&kT_f, g_kT_f);
    cudaGetSymbolAddress((void**)&ow_f, g_ow_f);

    // 0a) segmented conversion (fp16 single planes)
    {
        ConvTable t;
        size_t off = 0;
        auto add = [&](int i, const float* s, __half* h, size_t n) {
            t.seg[i] = {s, h, off};
            off += n / 4;
        };
        add(0, hs,     hs_f,  (size_t)MS_ * H_);
        add(1, q_a_w,  pw_f,  (size_t)Q_LORA_ * H_);
        add(2, kv_a_w, pw_f + (size_t)Q_LORA_ * H_, (size_t)CAT_ * H_);
        add(3, q_b_w,  qbw_f, (size_t)N_ * QK_ * Q_LORA_);
        add(4, kv_b_w, kvbw_f,(size_t)N_ * (NOPE_+V_) * KV_LORA_);
        add(5, o_w,    ow_f,  (size_t)H_ * N_ * V_);
        t.total = off;
        conv_all<<<(unsigned)((t.total + 255) / 256), 256>>>(t);
    }
    // 0b) W_UK transpose (fp16 single)
    {
        size_t n = (size_t)N_ * KV_LORA_ * NOPE_;
        conv_ukT<<<(unsigned)((n + 255) / 256), 256>>>(kv_b_w, ukT_f);
    }

    // 1) merged projection [q_a | kv_a] = hs @ pw^T (N=2112 -> NT=64 path)
    run_gemm<64,256,0,false,false>({hs_f, pw_f, qkva, nullptr,
        MS_, PROJ_, H_, H_, H_, PROJ_, 0,0, 0,0, 0,0, 1,1});

    // 2) rmsnorm q_a slice -> qan fp16
    rmsnorm_f16<<<MS_, 256>>>(qkva, q_a_ln_w, qan_f, Q_LORA_, PROJ_);

    // 3) kv slice -> kcat/kT fp16
    kv_process_f16<<<MS_, 256>>>(qkva + Q_LORA_, kv_a_ln_w, cosb, sinb, pid, PROJ_,
                                 kcat_f, kT_f);

    // 4) q = qan @ q_b_w^T -> q fp16 (NT=128)
    run_gemm<128,512,2,false,false>({qan_f, qbw_f, nullptr, q_f,
        MS_, N_ * QK_, Q_LORA_, Q_LORA_, Q_LORA_, N_ * QK_, 0,0, 0,0, 0,0, 1,1});

    // 5) q_pe rope -> qcat fp16 (pe section)
    {
        size_t total = (size_t)MS_ * N_ * 32;
        q_rope_f16<<<(unsigned)((total + 255) / 256), 256>>>(q_f, cosb, sinb, pid, qcat_f);
    }

    // 6) q_lat = q_nope @ W_UK^T -> qcat fp16; batch n=64 (NT=128)
    run_gemm<128,512,2,false,false>({q_f, ukT_f, nullptr, qcat_f,
        MS_, KV_LORA_, NOPE_,
        N_ * QK_, NOPE_, N_ * CAT_,
        0, QK_, 0, (long long)KV_LORA_ * NOPE_, 0, CAT_,
        1, N_});

    // 7) scores = qcat @ kcat^T (causal skip, fp32 out); batch (b,n) (NT=128)
    run_gemm<128,512,0,true,false>({qcat_f, kcat_f, scores, nullptr,
        S_, S_, CAT_,
        N_ * CAT_, CAT_, S_,
        (long long)S_ * N_ * CAT_, CAT_,
        (long long)S_ * CAT_, 0,
        (long long)N_ * S_ * S_, (long long)S_ * S_,
        B_, N_});

    // 8) softmax -> attn fp16
    softmax_f16<<<B_ * N_ * S_, 256>>>(scores, attn_f);

    // 9) out_lat = attn @ ckv (K clip) -> ol fp16; batch (b,n) (NT=128)
    run_gemm<128,512,2,false,true>({attn_f, kT_f, nullptr, ol_f,
        S_, KV_LORA_, S_,
        S_, S_, N_ * KV_LORA_,
        (long long)N_ * S_ * S_, (long long)S_ * S_,
        (long long)KV_LORA_ * S_, 0,
        (long long)S_ * N_ * KV_LORA_, KV_LORA_,
        B_, N_});

    // 10) out_pre = out_lat @ W_UV^T -> op fp16; batch n=64 (NT=128)
    run_gemm<128,512,2,false,false>({ol_f, kvbw_f + (size_t)NOPE_ * KV_LORA_, nullptr, op_f,
        MS_, V_, KV_LORA_,
        N_ * KV_LORA_, KV_LORA_, N_ * V_,
        0, KV_LORA_,
        0, (long long)(NOPE_+V_) * KV_LORA_,
        0, V_,
        1, N_});

    // 11) out = out_pre @ o_w^T (fp32 to d_out) (NT=128)
    run_gemm<128,512,0,false,false>({op_f, ow_f, out, nullptr,
        MS_, H_, N_ * V_, N_ * V_, N_ * V_, H_, 0,0, 0,0, 0,0, 1,1});
}

// round 17
// speedup vs baseline: 1.0978x; 1.0978x over previous
#include <cuda_runtime.h>
#include <cuda_bf16.h>
#include <cuda_fp16.h>
#include <cstdint>

// ---------------------------------------------------------------------------
// Problem constants
// ---------------------------------------------------------------------------
constexpr int B_  = 2;
constexpr int S_  = 1024;
constexpr int H_  = 4096;
constexpr int N_  = 64;
constexpr int NOPE_ = 128;
constexpr int ROPE_ = 64;
constexpr int V_  = 128;
constexpr int KV_LORA_ = 512;
constexpr int Q_LORA_  = 1536;
constexpr int QK_ = NOPE_ + ROPE_;           // 192
constexpr int CAT_ = KV_LORA_ + ROPE_;       // 576
constexpr int PROJ_ = Q_LORA_ + CAT_;        // 2112
constexpr int MS_ = B_ * S_;                 // 2048
constexpr float SCALE_ = 0.072168783648703220563f; // 192^-0.5
constexpr float EPS_ = 1e-6f;

// ---------------------------------------------------------------------------
// Scratch (device globals; allocation is forbidden)
// ---------------------------------------------------------------------------
__device__ float g_qkva  [(size_t)MS_ * PROJ_];
__device__ float g_scores[(size_t)B_ * N_ * S_ * S_];

__device__ __half g_hs_f  [(size_t)MS_ * H_];
__device__ __half g_qan_f [(size_t)MS_ * Q_LORA_];
__device__ __half g_q_f   [(size_t)MS_ * N_ * QK_];
__device__ __half g_qcat_f[(size_t)MS_ * N_ * CAT_];
__device__ __half g_attn_f[(size_t)B_ * N_ * S_ * S_];
__device__ __half g_ol_f  [(size_t)MS_ * N_ * KV_LORA_];
__device__ __half g_op_f  [(size_t)MS_ * N_ * V_];

__device__ __half g_pw_f [(size_t)PROJ_ * H_];
__device__ __half g_qbw_f[(size_t)N_ * QK_ * Q_LORA_];
__device__ __half g_ukT_f[(size_t)N_ * KV_LORA_ * NOPE_];
__device__ __half g_kvbw_f[(size_t)N_ * (NOPE_+V_) * KV_LORA_];
__device__ __half g_kcat_f[(size_t)MS_ * CAT_];
__device__ __half g_kT_f [(size_t)B_ * KV_LORA_ * S_];
__device__ __half g_ow_f [(size_t)H_ * N_ * V_];

// ---------------------------------------------------------------------------
// PTX helpers
// ---------------------------------------------------------------------------
__device__ __forceinline__ void ldsm4(uint32_t* r, const void* p) {
    uint32_t addr = (uint32_t)__cvta_generic_to_shared(p);
    asm volatile("ldmatrix.sync.aligned.m8n8.x4.shared.b16 {%0,%1,%2,%3}, [%4];"
                 : "=r"(r[0]), "=r"(r[1]), "=r"(r[2]), "=r"(r[3]) : "r"(addr));
}
__device__ __forceinline__ void mma_f16(float* d, const uint32_t* a,
                                        uint32_t b0, uint32_t b1) {
    asm volatile("mma.sync.aligned.m16n8k16.row.col.f32.f16.f16.f32 "
                 "{%0,%1,%2,%3}, {%4,%5,%6,%7}, {%8,%9}, {%0,%1,%2,%3};"
                 : "+f"(d[0]), "+f"(d[1]), "+f"(d[2]), "+f"(d[3])
                 : "r"(a[0]), "r"(a[1]), "r"(a[2]), "r"(a[3]), "r"(b0), "r"(b1));
}
__device__ __forceinline__ void cp16(void* dst, const void* src) {
    uint32_t d = (uint32_t)__cvta_generic_to_shared(dst);
    asm volatile("cp.async.cg.shared.global [%0], [%1], 16;\n" :: "r"(d), "l"(src));
}
__device__ __forceinline__ void cp_commit() { asm volatile("cp.async.commit_group;\n"); }
template <int W> __device__ __forceinline__ void cp_wait() {
    asm volatile("cp.async.wait_group %0;\n" :: "n"(W));
}

// ---------------------------------------------------------------------------
// fp16 1-term GEMM: C = A @ B^T, single fp16 planes.
// 128x64 tile, K-step 64 (halves per-iter fixed overhead vs 32),
// 256 thr, 8 warps (4m x 2n, warp tile 32x32), 3-stage cp.async,
// 2 CTAs/SM, single sync per iter, 8-deep accumulator ILP.
// OMODE: 0=fp32 out, 2=fp16 out.
// CSKIP: skip tiles above causal diagonal. CKLIM: clip K at m0+128.
// Requires K % 64 == 0 (holds for all shapes here).
// ---------------------------------------------------------------------------
constexpr int SKA = 72;                     // 64 halves + 8 pad (144B, odd*16B)
constexpr int TPB = 256;
constexpr int NT  = 64;

#define A_EL_        (128 * SKA)            // 9216 halves
#define B_EL_        (NT * SKA)             // 4608 halves
#define STAGE_EL_    (A_EL_ + B_EL_)        // 13824 halves = 27648 B
#define SMEM_BYTES_  (3 * STAGE_EL_ * 2)    // 82944 B

extern __shared__ uint16_t smem_dyn[];

template <int OMODE, bool CSKIP, bool CKLIM>
__global__ __launch_bounds__(TPB, 2)
void gemm_f(const __half* __restrict__ A_,
            const __half* __restrict__ B_p,
            float* __restrict__ Cf, __half* __restrict__ Ch_,
            int K, int lda, int ldb, int ldc,
            long long sA1, long long sA2,
            long long sB1, long long sB2,
            long long sC1, long long sC2, int D2)
{
    constexpr int MSUB = 2;
    constexpr int STG  = STAGE_EL_;

    const int m0 = blockIdx.y * 128;
    const int n0 = blockIdx.x * NT;
    if (CSKIP && n0 > m0 + 127) return;

    const int tid  = threadIdx.x;
    const int lane = tid & 31;
    const int w    = tid >> 5;
    const int wm   = w & 3;
    const int wn   = w >> 2;

    const int bz = blockIdx.z;
    const int i1 = bz / D2;
    const int i2 = bz - i1 * D2;
    const long long offA = (long long)i1 * sA1 + (long long)i2 * sA2;
    const long long offB = (long long)i1 * sB1 + (long long)i2 * sB2;
    const long long offC = (long long)i1 * sC1 + (long long)i2 * sC2;
    const uint16_t* Ab = (const uint16_t*)A_  + offA;
    const uint16_t* Bb = (const uint16_t*)B_p + offB;

    int Keff = K;
    if (CKLIM) Keff = (K < m0 + 128) ? K : (m0 + 128);
    const int nk = Keff >> 6;               // 64-wide K chunks

    float acc[MSUB][4][4];
    #pragma unroll
    for (int i = 0; i < MSUB; i++)
        #pragma unroll
        for (int j = 0; j < 4; j++)
            #pragma unroll
            for (int t = 0; t < 4; t++) acc[i][j][t] = 0.f;

    auto load_stage = [&](int stg, int k0) {
        uint16_t* base = smem_dyn + stg * STG;
        #pragma unroll
        for (int j = 0; j < 4; j++) {          // A: 1024 16B chunks (128r x 8c)
            int idx = tid + j * TPB;
            int r = idx >> 3;
            int c = idx & 7;
            const uint16_t* src = Ab + (size_t)(m0 + r) * lda + k0 + c * 8;
            cp16(base + r * SKA + c * 8, src);
        }
        #pragma unroll
        for (int j = 0; j < 2; j++) {          // B: 512 16B chunks (64r x 8c)
            int idx = tid + j * TPB;
            int r = idx >> 3;
            int c = idx & 7;
            const uint16_t* src = Bb + (size_t)(n0 + r) * ldb + k0 + c * 8;
            cp16(base + A_EL_ + r * SKA + c * 8, src);
        }
    };

    load_stage(0, 0);
    cp_commit();
    if (nk > 1) load_stage(1, 64);
    cp_commit();

    int stg = 0;
    for (int i = 0; i < nk; i++) {
        cp_wait<1>();
        __syncthreads();
        int nxt = stg + 2; if (nxt >= 3) nxt -= 3;
        if (i + 2 < nk) load_stage(nxt, (i + 2) << 6);
        cp_commit();

        const uint16_t* sA = smem_dyn + stg * STG;
        const uint16_t* sB = sA + A_EL_;

        #pragma unroll
        for (int kk = 0; kk < 64; kk += 16) {
            uint32_t af[MSUB][4];
            const int ar = wm * 32 + (lane & 15);
            const int ac = kk + ((lane >> 4) << 3);
            #pragma unroll
            for (int mi = 0; mi < MSUB; mi++)
                ldsm4(af[mi], sA + (ar + mi * 16) * SKA + ac);

            uint32_t bf[2][4];
            const int br = wn * 32 + (lane & 7) + ((lane >> 4) << 3);
            const int bc = kk + (((lane >> 3) & 1) << 3);
            ldsm4(bf[0], sB + br * SKA + bc);
            ldsm4(bf[1], sB + (br + 16) * SKA + bc);

            // 8 independent accumulators between RAW reuses
            #pragma unroll
            for (int mi = 0; mi < MSUB; mi++) {
                #pragma unroll
                for (int ni = 0; ni < 4; ni++) {
                    const int p = ni >> 1, q = (ni & 1) * 2;
                    mma_f16(acc[mi][ni], af[mi], bf[p][q], bf[p][q + 1]);
                }
            }
        }
        stg = stg + 1; if (stg == 3) stg = 0;
    }

    // epilogue
    const int lr = lane >> 2;
    const int lc = (lane & 3) * 2;
    #pragma unroll
    for (int mi = 0; mi < MSUB; mi++) {
        #pragma unroll
        for (int ni = 0; ni < 4; ni++) {
            size_t row = (size_t)(m0 + wm * 32 + mi * 16 + lr);
            int    col = n0 + wn * 32 + ni * 8 + lc;
            size_t o0 = offC + row * ldc + col;
            size_t o1 = offC + (row + 8) * ldc + col;
            if (OMODE == 0) {
                *(float2*)&Cf[o0] = make_float2(acc[mi][ni][0], acc[mi][ni][1]);
                *(float2*)&Cf[o1] = make_float2(acc[mi][ni][2], acc[mi][ni][3]);
            } else {
                *(__half2*)&Ch_[o0] = {__float2half(acc[mi][ni][0]), __float2half(acc[mi][ni][1])};
                *(__half2*)&Ch_[o1] = {__float2half(acc[mi][ni][2]), __float2half(acc[mi][ni][3])};
            }
        }
    }
}

// ---------------------------------------------------------------------------
// Segmented conversion: fp32 -> fp16 single plane
// ---------------------------------------------------------------------------
struct ConvSeg { const float* s; __half* h; size_t off; };
struct ConvTable { ConvSeg seg[6]; size_t total; };

__global__ void conv_all(ConvTable t)
{
    size_t i = (size_t)blockIdx.x * blockDim.x + threadIdx.x;
    if (i >= t.total) return;
    int k = 0;
    #pragma unroll
    for (int j = 1; j < 6; j++) if (i >= t.seg[j].off) k = j;
    size_t li = i - t.seg[k].off;
    float4 v = ((const float4*)t.seg[k].s)[li];
    ((__half2*)t.seg[k].h)[2*li]   = {__float2half(v.x), __float2half(v.y)};
    ((__half2*)t.seg[k].h)[2*li+1] = {__float2half(v.z), __float2half(v.w)};
}

__global__ void conv_ukT(const float* __restrict__ w, __half* __restrict__ h)
{
    size_t i = (size_t)blockIdx.x * blockDim.x + threadIdx.x;
    if (i >= (size_t)N_ * KV_LORA_ * NOPE_) return;
    int d = (int)(i & (NOPE_ - 1));
    int c = (int)((i >> 7) & (KV_LORA_ - 1));
    int n = (int)(i >> 16);
    h[i] = __float2half(w[(size_t)n * ((NOPE_+V_) * KV_LORA_) + (size_t)d * KV_LORA_ + c]);
}

__global__ void rmsnorm_f16(const float* __restrict__ x, const float* __restrict__ w,
                            __half* __restrict__ of, int cols, int ld)
{
    __shared__ float red[256];
    const float* row = x + (size_t)blockIdx.x * ld;
    __half* rf = of + (size_t)blockIdx.x * cols;
    int tid = threadIdx.x;
    float ss = 0.f;
    for (int c = tid; c < cols; c += 256) { float v = row[c]; ss += v * v; }
    red[tid] = ss; __syncthreads();
    for (int o = 128; o > 0; o >>= 1) { if (tid < o) red[tid] += red[tid + o]; __syncthreads(); }
    float r = rsqrtf(red[0] / cols + EPS_);
    for (int c = tid; c < cols; c += 256) rf[c] = __float2half(row[c] * r * w[c]);
}

__global__ void kv_process_f16(const float* __restrict__ kva, const float* __restrict__ lnw,
                               const float* __restrict__ cosb, const float* __restrict__ sinb,
                               const int* __restrict__ pid, int ld,
                               __half* __restrict__ kcf, __half* __restrict__ kTf)
{
    __shared__ float red[256];
    int row = blockIdx.x;
    int b = row >> 10, t = row & (S_ - 1);
    const float* x = kva + (size_t)row * ld;
    __half* y = kcf + (size_t)row * CAT_;
    int tid = threadIdx.x;
    float ss = 0.f;
    for (int c = tid; c < KV_LORA_; c += 256) { float v = x[c]; ss += v * v; }
    red[tid] = ss; __syncthreads();
    for (int o = 128; o > 0; o >>= 1) { if (tid < o) red[tid] += red[tid + o]; __syncthreads(); }
    float r = rsqrtf(red[0] / KV_LORA_ + EPS_);
    for (int c = tid; c < KV_LORA_; c += 256) {
        __half h = __float2half(x[c] * r * lnw[c]);
        y[c] = h;
        kTf[((size_t)b * KV_LORA_ + c) * S_ + t] = h;
    }
    if (tid < 32) {
        int pos = pid[row];
        const float* cp = cosb + (size_t)pos * ROPE_;
        const float* sp = sinb + (size_t)pos * ROPE_;
        int i = tid;
        float x1 = x[KV_LORA_ + i], x2 = x[KV_LORA_ + i + 32];
        y[KV_LORA_ + i]      = __float2half(x1 * cp[i] - x2 * sp[i]);
        y[KV_LORA_ + i + 32] = __float2half(x2 * cp[i + 32] + x1 * sp[i + 32]);
    }
}

__global__ void q_rope_f16(const __half* __restrict__ qf,
                           const float* __restrict__ cosb, const float* __restrict__ sinb,
                           const int* __restrict__ pid, __half* __restrict__ ocf)
{
    size_t idx = (size_t)blockIdx.x * blockDim.x + threadIdx.x;
    if (idx >= (size_t)MS_ * N_ * 32) return;
    int i = (int)(idx & 31);
    size_t r = idx >> 5;
    int n = (int)(r & (N_ - 1));
    size_t m = r >> 6;
    int pos = pid[m];
    size_t src = m * (size_t)(N_ * QK_) + (size_t)n * QK_ + NOPE_;
    size_t dst = m * (size_t)(N_ * CAT_) + (size_t)n * CAT_ + KV_LORA_;
    float x1 = __half2float(qf[src + i]);
    float x2 = __half2float(qf[src + i + 32]);
    float c1 = cosb[(size_t)pos * ROPE_ + i],      s1 = sinb[(size_t)pos * ROPE_ + i];
    float c2 = cosb[(size_t)pos * ROPE_ + i + 32], s2 = sinb[(size_t)pos * ROPE_ + i + 32];
    ocf[dst + i]      = __float2half(x1 * c1 - x2 * s1);
    ocf[dst + i + 32] = __float2half(x2 * c2 + x1 * s2);
}

__global__ void softmax_f16(float* __restrict__ scores, __half* __restrict__ af)
{
    __shared__ float red[256];
    int r = blockIdx.x;
    int s = r & (S_ - 1);
    float* x = scores + (size_t)r * S_;
    __half* of = af + (size_t)r * S_;
    int tid = threadIdx.x;

    float mx = -1e30f;
    for (int t = tid; t <= s; t += 256) mx = fmaxf(mx, x[t] * SCALE_);
    red[tid] = mx; __syncthreads();
    for (int o = 128; o > 0; o >>= 1) { if (tid < o) red[tid] = fmaxf(red[tid], red[tid + o]); __syncthreads(); }
    mx = red[0]; __syncthreads();

    float sum = 0.f;
    for (int t = tid; t <= s; t += 256) {
        float e = __expf(x[t] * SCALE_ - mx);
        x[t] = e;
        sum += e;
    }
    red[tid] = sum; __syncthreads();
    for (int o = 128; o > 0; o >>= 1) { if (tid < o) red[tid] += red[tid + o]; __syncthreads(); }
    float inv = 1.f / red[0];

    for (int t = tid; t <= s; t += 256) of[t] = __float2half(x[t] * inv);
    int zend = ((s >> 7) + 1) << 7;
    __half z = __float2half(0.f);
    for (int t = s + 1 + tid; t < zend; t += 256) of[t] = z;
}

// ---------------------------------------------------------------------------
// Host launch
// ---------------------------------------------------------------------------
struct GArgs {
    const __half *A, *Bp;
    float* Cf; __half* Ch;
    int M, N, K, lda, ldb, ldc;
    long long sA1, sA2, sB1, sB2, sC1, sC2;
    int D1, D2;
};

template <int OMODE, bool CSKIP, bool CKLIM>
static inline void run_gemm(const GArgs& a)
{
    dim3 grid(a.N / NT, a.M / 128, a.D1 * a.D2);
    gemm_f<OMODE, CSKIP, CKLIM><<<grid, TPB, SMEM_BYTES_>>>(
        a.A, a.Bp, a.Cf, a.Ch,
        a.K, a.lda, a.ldb, a.ldc, a.sA1, a.sA2, a.sB1, a.sB2, a.sC1, a.sC2, a.D2);
}

extern "C" void kernel_launch(void* const* d_in, const int* in_sizes, int n_in,
                              void* d_out, int out_size)
{
    const float* hs        = (const float*)d_in[0];
    const int*   pid       = (const int*)d_in[1];
    const float* cosb      = (const float*)d_in[2];
    const float* sinb      = (const float*)d_in[3];
    const float* q_a_w     = (const float*)d_in[4];
    const float* q_a_ln_w  = (const float*)d_in[5];
    const float* q_b_w     = (const float*)d_in[6];
    const float* kv_a_w    = (const float*)d_in[7];
    const float* kv_a_ln_w = (const float*)d_in[8];
    const float* kv_b_w    = (const float*)d_in[9];
    const float* o_w       = (const float*)d_in[10];
    float*       out       = (float*)d_out;

    static bool attr_set = false;
    if (!attr_set) {
        cudaFuncSetAttribute(gemm_f<0,false,false>, cudaFuncAttributeMaxDynamicSharedMemorySize, SMEM_BYTES_);
        cudaFuncSetAttribute(gemm_f<2,false,false>, cudaFuncAttributeMaxDynamicSharedMemorySize, SMEM_BYTES_);
        cudaFuncSetAttribute(gemm_f<0,true, false>, cudaFuncAttributeMaxDynamicSharedMemorySize, SMEM_BYTES_);
        cudaFuncSetAttribute(gemm_f<2,false,true >, cudaFuncAttributeMaxDynamicSharedMemorySize, SMEM_BYTES_);
        attr_set = true;
    }

    float *qkva, *scores;
    cudaGetSymbolAddress((void**)&qkva,   g_qkva);
    cudaGetSymbolAddress((void**)&scores, g_scores);

    __half *hs_f,*qan_f,*q_f,*qcat_f,*attn_f,*ol_f,*op_f;
    __half *pw_f,*qbw_f,*ukT_f,*kvbw_f,*kcat_f,*kT_f,*ow_f;
    cudaGetSymbolAddress((void**)&hs_f, g_hs_f);
    cudaGetSymbolAddress((void**)&qan_f, g_qan_f);
    cudaGetSymbolAddress((void**)&q_f, g_q_f);
    cudaGetSymbolAddress((void**)&qcat_f, g_qcat_f);
    cudaGetSymbolAddress((void**)&attn_f, g_attn_f);
    cudaGetSymbolAddress((void**)&ol_f, g_ol_f);
    cudaGetSymbolAddress((void**)&op_f, g_op_f);
    cudaGetSymbolAddress((void**)&pw_f, g_pw_f);
    cudaGetSymbolAddress((void**)&qbw_f, g_qbw_f);
    cudaGetSymbolAddress((void**)&ukT_f, g_ukT_f);
    cudaGetSymbolAddress((void**)&kvbw_f, g_kvbw_f);
    cudaGetSymbolAddress((void**)&kcat_f, g_kcat_f);
    cudaGetSymbolAddress((void**)&kT_f, g_kT_f);
    cudaGetSymbolAddress((void**)&ow_f, g_ow_f);

    // 0a) segmented conversion (fp16 single planes)
    {
        ConvTable t;
        size_t off = 0;
        auto add = [&](int i, const float* s, __half* h, size_t n) {
            t.seg[i] = {s, h, off};
            off += n / 4;
        };
        add(0, hs,     hs_f,  (size_t)MS_ * H_);
        add(1, q_a_w,  pw_f,  (size_t)Q_LORA_ * H_);
        add(2, kv_a_w, pw_f + (size_t)Q_LORA_ * H_, (size_t)CAT_ * H_);
        add(3, q_b_w,  qbw_f, (size_t)N_ * QK_ * Q_LORA_);
        add(4, kv_b_w, kvbw_f,(size_t)N_ * (NOPE_+V_) * KV_LORA_);
        add(5, o_w,    ow_f,  (size_t)H_ * N_ * V_);
        t.total = off;
        conv_all<<<(unsigned)((t.total + 255) / 256), 256>>>(t);
    }
    // 0b) W_UK transpose (fp16 single)
    {
        size_t n = (size_t)N_ * KV_LORA_ * NOPE_;
        conv_ukT<<<(unsigned)((n + 255) / 256), 256>>>(kv_b_w, ukT_f);
    }

    // 1) merged projection [q_a | kv_a] = hs @ pw^T (fp32 out)
    run_gemm<0,false,false>({hs_f, pw_f, qkva, nullptr,
        MS_, PROJ_, H_, H_, H_, PROJ_, 0,0, 0,0, 0,0, 1,1});

    // 2) rmsnorm q_a slice -> qan fp16
    rmsnorm_f16<<<MS_, 256>>>(qkva, q_a_ln_w, qan_f, Q_LORA_, PROJ_);

    // 3) kv slice -> kcat/kT fp16
    kv_process_f16<<<MS_, 256>>>(qkva + Q_LORA_, kv_a_ln_w, cosb, sinb, pid, PROJ_,
                                 kcat_f, kT_f);

    // 4) q = qan @ q_b_w^T -> q fp16
    run_gemm<2,false,false>({qan_f, qbw_f, nullptr, q_f,
        MS_, N_ * QK_, Q_LORA_, Q_LORA_, Q_LORA_, N_ * QK_, 0,0, 0,0, 0,0, 1,1});

    // 5) q_pe rope -> qcat fp16 (pe section)
    {
        size_t total = (size_t)MS_ * N_ * 32;
        q_rope_f16<<<(unsigned)((total + 255) / 256), 256>>>(q_f, cosb, sinb, pid, qcat_f);
    }

    // 6) q_lat = q_nope @ W_UK^T -> qcat fp16; batch n=64
    run_gemm<2,false,false>({q_f, ukT_f, nullptr, qcat_f,
        MS_, KV_LORA_, NOPE_,
        N_ * QK_, NOPE_, N_ * CAT_,
        0, QK_, 0, (long long)KV_LORA_ * NOPE_, 0, CAT_,
        1, N_});

    // 7) scores = qcat @ kcat^T (causal skip, fp32 out); batch (b,n)
    run_gemm<0,true,false>({qcat_f, kcat_f, scores, nullptr,
        S_, S_, CAT_,
        N_ * CAT_, CAT_, S_,
        (long long)S_ * N_ * CAT_, CAT_,
        (long long)S_ * CAT_, 0,
        (long long)N_ * S_ * S_, (long long)S_ * S_,
        B_, N_});

    // 8) softmax -> attn fp16
    softmax_f16<<<B_ * N_ * S_, 256>>>(scores, attn_f);

    // 9) out_lat = attn @ ckv (K clip) -> ol fp16; batch (b,n)
    run_gemm<2,false,true>({attn_f, kT_f, nullptr, ol_f,
        S_, KV_LORA_, S_,
        S_, S_, N_ * KV_LORA_,
        (long long)N_ * S_ * S_, (long long)S_ * S_,
        (long long)KV_LORA_ * S_, 0,
        (long long)S_ * N_ * KV_LORA_, KV_LORA_,
        B_, N_});

    // 10) out_pre = out_lat @ W_UV^T -> op fp16; batch n=64
    run_gemm<2,false,false>({ol_f, kvbw_f + (size_t)NOPE_ * KV_LORA_, nullptr, op_f,
        MS_, V_, KV_LORA_,
        N_ * KV_LORA_, KV_LORA_, N_ * V_,
        0, KV_LORA_,
        0, (long long)(NOPE_+V_) * KV_LORA_,
        0, V_,
        1, N_});

    // 11) out = out_pre @ o_w^T (fp32 to d_out)
    run_gemm<0,false,false>({op_f, ow_f, out, nullptr,
        MS_, H_, N_ * V_, N_ * V_, N_ * V_, H_, 0,0, 0,0, 0,0, 1,1});
}